// round 17
// baseline (speedup 1.0000x reference)
#include <cuda_runtime.h>
#include <cstdint>
#include <cfloat>

typedef unsigned int u32;

#define N_ROWS  32768
#define C_DIM   256
#define K_CODES 1024
#define NCB     8          // code-blocks of 128
#define NCHUNK  8          // chunks of 32 c (K logical = 256, hi*hi only)
#define E2      0.5f       // 2*E; validated R7-R16
#define NSTAGE  3
#define A_STRIDE 132
#define A_FLOATS (32 * A_STRIDE)          // 4224
#define A_BYTES  (A_FLOATS * 4)           // 16896
#define STAGE_BYTES (A_BYTES + 16384)     // 33280
#define SMEM_MMA (NSTAGE * STAGE_BYTES)   // 99840; also holds dist + top4 overlays
#define DSTRIDE 133                       // scan banks stride 5 mod 32: conflict-free
#define OFF_SD4 20000                     // float4 top-4 vals [2][128] (overlay)
#define OFF_SI4 21024                     // int4 top-4 idx  [2][128] (overlay)
#define SMEM_POST (64 * 257 * 4)          // 65792 -> 2 CTAs/SM

// efr: [code_tile(128)][kt(32)][lane 32][reg 2]  (tf32 hi of -2*emb)
__device__ float efr[(size_t)(K_CODES / 8) * 32 * 64];
__device__ float embT[C_DIM * K_CODES];    // [c][k] = -2*emb[k][c], exact fp32
__device__ float g_enorm[K_CODES];
__device__ float4 g_tv4[NCB * N_ROWS];     // per (cb,row): top-4 approx dists (sorted)
__device__ int4   g_ti4[NCB * N_ROWS];     // matching code indices
__device__ float g_partial[256];           // per-post-block sum of chosen dist
__device__ float g_zsq[256];               // per-rowblock sum ||z||^2 (from k_mma cb==0)
__device__ int   g_done;                   // zero-init at load; k_zero re-arms post-replay

// ---------------- helpers ----------------
__device__ __forceinline__ u32 smem_u32(const void* p) {
    return (u32)__cvta_generic_to_shared(p);
}
__device__ __forceinline__ void cp16(u32 dst, const void* src) {
    asm volatile("cp.async.cg.shared.global [%0], [%1], 16;" :: "r"(dst), "l"(src));
}
__device__ __forceinline__ u32 tf32u(float v) {
    u32 r; asm("cvt.rna.satfinite.tf32.f32 %0, %1;" : "=r"(r) : "f"(v));
    return r;
}
__device__ __forceinline__ void mma8(float* d, uint4 a, uint2 b) {
    asm("mma.sync.aligned.m16n8k8.row.col.f32.tf32.tf32.f32 "
        "{%0,%1,%2,%3}, {%4,%5,%6,%7}, {%8,%9}, {%0,%1,%2,%3};"
        : "+f"(d[0]), "+f"(d[1]), "+f"(d[2]), "+f"(d[3])
        : "r"(a.x), "r"(a.y), "r"(a.z), "r"(a.w), "r"(b.x), "r"(b.y));
}
__device__ __forceinline__ bool lessp(float va, int ia, float vb, int ib) {
    return va < vb || (va == vb && ia < ib);
}
// constant-index sorted insert into bv[0..3] (ascending)
__device__ __forceinline__ void ins4(float v, int k, float* bv, int* bi) {
    if (lessp(v, k, bv[3], bi[3])) {
        bv[3] = v; bi[3] = k;
        if (lessp(bv[3], bi[3], bv[2], bi[2])) {
            float tv = bv[2]; bv[2] = bv[3]; bv[3] = tv;
            int ti = bi[2]; bi[2] = bi[3]; bi[3] = ti;
        }
        if (lessp(bv[2], bi[2], bv[1], bi[1])) {
            float tv = bv[1]; bv[1] = bv[2]; bv[2] = tv;
            int ti = bi[1]; bi[1] = bi[2]; bi[2] = ti;
        }
        if (lessp(bv[1], bi[1], bv[0], bi[0])) {
            float tv = bv[0]; bv[0] = bv[1]; bv[1] = tv;
            int ti = bi[0]; bi[0] = bi[1]; bi[1] = ti;
        }
    }
}
__device__ __forceinline__ void cswap(float& va, int& ia, float& vb, int& ib) {
    bool sw = lessp(vb, ib, va, ia);
    float v0 = sw ? vb : va, v1 = sw ? va : vb;
    int   i0 = sw ? ib : ia, i1 = sw ? ia : ib;
    va = v0; vb = v1; ia = i0; ib = i1;
}
__device__ __forceinline__ void sort4_bitonic(float* w, int* wi) {
    cswap(w[0], wi[0], w[2], wi[2]);
    cswap(w[1], wi[1], w[3], wi[3]);
    cswap(w[0], wi[0], w[1], wi[1]);
    cswap(w[2], wi[2], w[3], wi[3]);
}
// merge two sorted 4-lists -> sorted top-4 (constant indices)
__device__ __forceinline__ void merge4_arrays(const float* av, const int* ai,
                                              const float* bv, const int* bi,
                                              float* rv, int* ri) {
    #pragma unroll
    for (int t = 0; t < 4; t++) {
        bool tm = lessp(av[t], ai[t], bv[3 - t], bi[3 - t]);
        rv[t] = tm ? av[t] : bv[3 - t];
        ri[t] = tm ? ai[t] : bi[3 - t];
    }
    sort4_bitonic(rv, ri);
}

// ---------------------------------------------------------------------------
// zero: re-arm the loss-reduction counter for the NEXT replay (runs last;
// g_done is zero-initialized at module load for the first execution)
// ---------------------------------------------------------------------------
__global__ void k_zero() { if (threadIdx.x == 0) g_done = 0; }

// ---------------------------------------------------------------------------
// prep (emb only): efr fragments + embT + norms. 128 blocks of 8 codes.
// ---------------------------------------------------------------------------
__global__ void __launch_bounds__(256)
k_prep(const float* __restrict__ emb)
{
    const int tid = threadIdx.x;
    const int ct = blockIdx.x;        // code tile (8 codes)
    const int k0 = ct * 8;
    for (int j = tid; j < 2048; j += 256) {
        int within = j & 63, kt = j >> 6;
        int lane = within >> 1, reg = within & 1;
        int code = k0 + (lane >> 2);
        int cmod = kt * 8 + (lane & 3) + reg * 4;
        efr[(size_t)(ct * 32 + kt) * 64 + within] =
            __uint_as_float(tf32u(-2.0f * emb[code * C_DIM + cmod]));
    }
    for (int j = tid; j < 2048; j += 256) {
        int c = j >> 3, kk = j & 7;
        embT[c * K_CODES + k0 + kk] = -2.0f * emb[(k0 + kk) * C_DIM + c];
    }
    int wid = tid >> 5, lane = tid & 31;
    int code = k0 + wid;
    const float4* p = (const float4*)(emb + code * C_DIM);
    float4 a = p[lane];
    float4 b = p[lane + 32];
    float s = a.x*a.x + a.y*a.y + a.z*a.z + a.w*a.w
            + b.x*b.x + b.y*b.y + b.z*b.z + b.w*b.w;
    #pragma unroll
    for (int m = 16; m; m >>= 1) s += __shfl_xor_sync(0xffffffffu, s, m);
    if (lane == 0) g_enorm[code] = s;
}

// ---------------------------------------------------------------------------
// main: tf32 mma.sync GEMM (hi*hi); smem-decoupled top-4 epilogue.
// All scratch (dist matrix, top-4 lists) overlays the dead stage buffers:
// static smem ~0.6KB -> 2 CTAs/SM guaranteed.
// ---------------------------------------------------------------------------
__device__ __forceinline__ void load_chunk(u32 base, int buf, int ch,
                                           int b, int hw0, int cb, int tid,
                                           const float* __restrict__ z_e)
{
    u32 dst = base + (u32)buf * STAGE_BYTES;
    #pragma unroll
    for (int t2 = 0; t2 < 4; t2++) {           // A: 32 c x 128 rows, direct from z_e
        int t = tid + t2 * 256;
        int c = t >> 5, part = t & 31;
        cp16(dst + (u32)(c * (A_STRIDE * 4) + part * 16),
             z_e + (((size_t)(b * C_DIM + ch * 32 + c)) << 10) + hw0 + part * 4);
    }
    #pragma unroll
    for (int t2 = 0; t2 < 4; t2++) {           // B: 4kt x 16nt x 256B = 16KB
        int t = tid + t2 * 256;
        int tile = t >> 4, part = t & 15;
        int kt = tile >> 4, nt = tile & 15;
        cp16(dst + (u32)A_BYTES + (u32)((tile << 8) + (part << 4)),
             (const char*)efr + ((((size_t)(cb * 16 + nt) * 32 + ch * 4 + kt) << 8) + (part << 4)));
    }
    asm volatile("cp.async.commit_group;");
}

__global__ void __launch_bounds__(256, 2)
k_mma(const float* __restrict__ z_e)
{
    extern __shared__ float smf[];
    __shared__ float en_s[128];
    __shared__ float wsum2[8];

    const int tid = threadIdx.x;
    const int lane = tid & 31, wid = tid >> 5;
    const int warp_m = wid & 3, warp_n = wid >> 2;
    const int cb = blockIdx.x;             // fast dim -> L2 reuse of z_e
    const int rb = blockIdx.y;
    const int r0 = rb * 128;
    const int b = r0 >> 10, hw0 = r0 & 1023;
    const u32 base = smem_u32(smf);

    if (tid < 128) en_s[tid] = g_enorm[cb * 128 + tid];

    float d[2][8][4];
    #pragma unroll
    for (int m = 0; m < 2; m++)
        #pragma unroll
        for (int n = 0; n < 8; n++)
            #pragma unroll
            for (int q = 0; q < 4; q++) d[m][n][q] = 0.0f;

    load_chunk(base, 0, 0, b, hw0, cb, tid, z_e);
    load_chunk(base, 1, 1, b, hw0, cb, tid, z_e);

    const int frow = (lane >> 2);
    const int fc   = (lane & 3);
    float zsq = 0.0f;

    for (int ch = 0; ch < NCHUNK; ch++) {
        int buf = ch % NSTAGE;
        if (ch < NCHUNK - 1) asm volatile("cp.async.wait_group 1;");
        else                 asm volatile("cp.async.wait_group 0;");
        __syncthreads();
        if (ch + 2 < NCHUNK) load_chunk(base, (ch + 2) % NSTAGE, ch + 2, b, hw0, cb, tid, z_e);

        const float* aS = smf + buf * (STAGE_BYTES / 4);
        const float* bS = aS + A_FLOATS;

        if (cb == 0) {                     // exact sum ||z||^2 (1/8 of CTAs)
            #pragma unroll
            for (int t2 = 0; t2 < 16; t2++) {
                int j = tid + t2 * 256;
                float v = aS[(j >> 7) * A_STRIDE + (j & 127)];
                zsq = fmaf(v, v, zsq);
            }
        }

        #pragma unroll
        for (int kt = 0; kt < 4; kt++) {
            uint4 a[2];
            uint2 bf[8];
            #pragma unroll
            for (int m = 0; m < 2; m++) {
                int rbase = warp_m * 32 + m * 16 + frow;
                int cbase = kt * 8 + fc;
                a[m].x = tf32u(aS[ cbase      * A_STRIDE + rbase    ]);
                a[m].y = tf32u(aS[ cbase      * A_STRIDE + rbase + 8]);
                a[m].z = tf32u(aS[(cbase + 4) * A_STRIDE + rbase    ]);
                a[m].w = tf32u(aS[(cbase + 4) * A_STRIDE + rbase + 8]);
            }
            #pragma unroll
            for (int n = 0; n < 8; n++)
                bf[n] = *(const uint2*)(bS + (((kt * 16 + warp_n * 8 + n) << 6) + (lane << 1)));
            #pragma unroll
            for (int m = 0; m < 2; m++)
                #pragma unroll
                for (int n = 0; n < 8; n++)
                    mma8(d[m][n], a[m], bf[n]);
        }
    }

    // ---- epilogue A: dump dist = acc + ||e||^2 into smem (d dies here) ----
    __syncthreads();                       // all warps done with stage buffers
    {
        const int g = lane >> 2, tq = lane & 3;
        const int wm0 = warp_m * 32, wn0 = warp_n * 64;
        #pragma unroll
        for (int m = 0; m < 2; m++)
            #pragma unroll
            for (int n = 0; n < 8; n++)
                #pragma unroll
                for (int q = 0; q < 4; q++) {
                    int row = wm0 + m * 16 + ((q >> 1) << 3) + g;
                    int col = wn0 + n * 8 + 2 * tq + (q & 1);
                    smf[row * DSTRIDE + col] = d[m][n][q] + en_s[col];
                }
    }

    if (cb == 0) {
        #pragma unroll
        for (int m = 16; m; m >>= 1) zsq += __shfl_xor_sync(0xffffffffu, zsq, m);
        if (lane == 0) wsum2[wid] = zsq;
    }
    __syncthreads();

    // ---- epilogue B: each half-thread scans 64 codes of one row ----
    {
        const int r = tid & 127, half = tid >> 7;
        const float* dr = smf + r * DSTRIDE + half * 64;
        float bv[4] = {FLT_MAX, FLT_MAX, FLT_MAX, FLT_MAX};
        int   bi_[4] = {0x7fffffff, 0x7fffffff, 0x7fffffff, 0x7fffffff};
        const int kbase = cb * 128 + half * 64;
        #pragma unroll 8
        for (int k = 0; k < 64; k++)
            ins4(dr[k], kbase + k, bv, bi_);
        float* sd4f = smf + OFF_SD4 + (half * 128 + r) * 4;
        int*   si4f = (int*)(smf + OFF_SI4) + (half * 128 + r) * 4;
        #pragma unroll
        for (int t = 0; t < 4; t++) { sd4f[t] = bv[t]; si4f[t] = bi_[t]; }
    }
    __syncthreads();
    if (tid < 128) {
        float av[4], bvv[4], rv[4]; int ai[4], bii[4], ri[4];
        const float* sd4f = smf + OFF_SD4;
        const int*   si4f = (const int*)(smf + OFF_SI4);
        float4 A4 = *(const float4*)(sd4f + tid * 4);
        float4 B4 = *(const float4*)(sd4f + (128 + tid) * 4);
        int4   Ai = *(const int4*)(si4f + tid * 4);
        int4   Bi = *(const int4*)(si4f + (128 + tid) * 4);
        av[0]=A4.x; av[1]=A4.y; av[2]=A4.z; av[3]=A4.w;
        ai[0]=Ai.x; ai[1]=Ai.y; ai[2]=Ai.z; ai[3]=Ai.w;
        bvv[0]=B4.x; bvv[1]=B4.y; bvv[2]=B4.z; bvv[3]=B4.w;
        bii[0]=Bi.x; bii[1]=Bi.y; bii[2]=Bi.z; bii[3]=Bi.w;
        merge4_arrays(av, ai, bvv, bii, rv, ri);
        size_t o = (size_t)cb * N_ROWS + r0 + tid;
        g_tv4[o] = make_float4(rv[0], rv[1], rv[2], rv[3]);
        g_ti4[o] = make_int4(ri[0], ri[1], ri[2], ri[3]);
    }
    if (cb == 0 && tid == 0) {
        float s = 0.0f;
        #pragma unroll
        for (int w = 0; w < 8; w++) s += wsum2[w];
        g_zsq[rb] = s;
    }
}

// ---------------------------------------------------------------------------
// post: pick + candidate refine (<=16 cands) + rare full rescue + gather/res
// + fused loss. esm staged in 64-row halves -> 2 CTAs/SM.
// ---------------------------------------------------------------------------
__global__ void __launch_bounds__(256, 2)
k_post(const float* __restrict__ z_e, const float* __restrict__ emb,
       float* __restrict__ res, float* __restrict__ out_idx_f,
       float* __restrict__ out_loss)
{
    extern __shared__ float esm[];           // 64 x 257
    __shared__ int   idx_sm[128];
    __shared__ float dist_sm[128];
    __shared__ int   full_list[128];
    __shared__ int   ref_list[128];
    __shared__ int   cand[128][16];
    __shared__ int   ccnt[128];
    __shared__ int   nfull_s, nref_s;
    __shared__ float zrow[256];
    __shared__ float wd[8]; __shared__ int wk[8];
    __shared__ float wsum[8];
    __shared__ int   lastflag;

    const int tid = threadIdx.x;
    const int wid = tid >> 5, lane = tid & 31;
    const int r0 = blockIdx.x * 128;
    const int b = r0 >> 10, hw0 = r0 & 1023;

    if (tid == 0) { nfull_s = 0; nref_s = 0; }
    __syncthreads();

    // classify using top-4 lists
    if (tid < 128) {
        int row = r0 + tid;
        float V1 = FLT_MAX; int bi = 0x7fffffff;
        float4 vv[NCB]; int4 kk[NCB];
        #pragma unroll
        for (int cb = 0; cb < NCB; cb++) {
            vv[cb] = g_tv4[(size_t)cb * N_ROWS + row];
            kk[cb] = g_ti4[(size_t)cb * N_ROWS + row];
            if (lessp(vv[cb].x, kk[cb].x, V1, bi)) { V1 = vv[cb].x; bi = kk[cb].x; }
        }
        idx_sm[tid] = bi;
        dist_sm[tid] = V1;
        float th = V1 + E2;
        bool unc = false; int nc = 0;
        #pragma unroll
        for (int cb = 0; cb < NCB; cb++) {
            if (vv[cb].w < th) unc = true;       // 4th-best too close: coverage risk
            if (vv[cb].x < th) { if (nc < 16) cand[tid][nc] = kk[cb].x; nc++; }
            if (vv[cb].y < th) { if (nc < 16) cand[tid][nc] = kk[cb].y; nc++; }
            if (vv[cb].z < th) { if (nc < 16) cand[tid][nc] = kk[cb].z; nc++; }
            if (vv[cb].w < th) { if (nc < 16) cand[tid][nc] = kk[cb].w; nc++; }
        }
        if (nc > 16) unc = true;                 // candidate overflow -> full scan
        if (unc) {
            full_list[atomicAdd(&nfull_s, 1)] = tid;
        } else if (nc > 1) {
            int p = atomicAdd(&nref_s, 1);
            ref_list[p] = tid;
            ccnt[tid] = nc;
        }
    }
    __syncthreads();

    // candidate refine: warp per entry, exact fp32 (also yields exact dist)
    for (int j = wid; j < nref_s; j += 8) {
        int rl = ref_list[j];
        int hw = hw0 + rl;
        float zreg[8];
        #pragma unroll
        for (int cc = 0; cc < 8; cc++)
            zreg[cc] = z_e[(((size_t)(b * C_DIM + cc * 32 + lane)) << 10) + hw];
        int nc = ccnt[rl];
        float bd = FLT_MAX; int bk = 0x7fffffff;
        for (int ci = 0; ci < nc; ci++) {
            int k = cand[rl][ci];
            const float* er = emb + (size_t)k * C_DIM;
            float acc = 0.0f;
            #pragma unroll
            for (int cc = 0; cc < 8; cc++)
                acc += zreg[cc] * er[cc * 32 + lane];
            #pragma unroll
            for (int m = 16; m; m >>= 1) acc += __shfl_xor_sync(0xffffffffu, acc, m);
            float dd = g_enorm[k] - 2.0f * acc;
            if (dd < bd || (dd == bd && k < bk)) { bd = dd; bk = k; }
        }
        if (lane == 0) { idx_sm[rl] = bk; dist_sm[rl] = bd; }
    }

    // full-scan rescue (rare): block-cooperative via embT
    int nfull = nfull_s;
    for (int j = 0; j < nfull; j++) {
        int rl = full_list[j];
        __syncthreads();
        zrow[tid] = z_e[(((size_t)(b * C_DIM + tid)) << 10) + hw0 + rl];
        __syncthreads();
        float bd = FLT_MAX; int bk = 0x7fffffff;
        #pragma unroll
        for (int gch = 0; gch < 4; gch++) {
            int k = wid * 128 + gch * 32 + lane;
            float acc = 0.0f;
            #pragma unroll 8
            for (int c = 0; c < C_DIM; c++)
                acc = fmaf(zrow[c], embT[c * K_CODES + k], acc);
            float dd = g_enorm[k] + acc;
            if (dd < bd) { bd = dd; bk = k; }   // k increasing -> ties keep lower k
        }
        #pragma unroll
        for (int m = 16; m; m >>= 1) {
            float obd = __shfl_xor_sync(0xffffffffu, bd, m);
            int   obk = __shfl_xor_sync(0xffffffffu, bk, m);
            if (obd < bd || (obd == bd && obk < bk)) { bd = obd; bk = obk; }
        }
        if (lane == 0) { wd[wid] = bd; wk[wid] = bk; }
        __syncthreads();
        if (tid == 0) {
            float B = FLT_MAX; int K = 0x7fffffff;
            #pragma unroll
            for (int w = 0; w < 8; w++)
                if (wd[w] < B || (wd[w] == B && wk[w] < K)) { B = wd[w]; K = wk[w]; }
            idx_sm[rl] = K;
            dist_sm[rl] = B;
        }
    }
    __syncthreads();

    if (tid < 128) out_idx_f[r0 + tid] = (float)idx_sm[tid];

    // gather + res write in 2 halves of 64 rows
    for (int hp = 0; hp < 2; hp++) {
        const int rbase = hp * 64;
        __syncthreads();
        for (int i = tid; i < 64 * 256; i += 256) {
            int r = i >> 8, c = i & 255;
            esm[r * 257 + c] = emb[idx_sm[rbase + r] * C_DIM + c];
        }
        __syncthreads();
        const int r = tid & 63, cq = tid >> 6;
        for (int cc = 0; cc < 256; cc += 4) {
            int c = cc + cq;
            res[(((size_t)(b * C_DIM + c)) << 10) + hw0 + rbase + r] = esm[r * 257 + c];
        }
    }

    // loss partial: sum of chosen distances over this block's rows
    float dv = (tid < 128) ? dist_sm[tid] : 0.0f;
    #pragma unroll
    for (int m = 16; m; m >>= 1) dv += __shfl_xor_sync(0xffffffffu, dv, m);
    if (lane == 0) wsum[wid] = dv;
    __syncthreads();
    if (tid == 0) {
        float s = 0.0f;
        #pragma unroll
        for (int w = 0; w < 8; w++) s += wsum[w];
        g_partial[blockIdx.x] = s;
        __threadfence();
        lastflag = (atomicAdd(&g_done, 1) == 255) ? 1 : 0;
    }
    __syncthreads();
    if (lastflag && wid == 0) {
        __threadfence();
        float s = 0.0f;
        for (int j = lane; j < 256; j += 32) s += g_partial[j] + g_zsq[j];
        #pragma unroll
        for (int m = 16; m; m >>= 1) s += __shfl_xor_sync(0xffffffffu, s, m);
        if (lane == 0) out_loss[0] = 1.25f * (s / 8388608.0f);
    }
}

// ---------------------------------------------------------------------------
extern "C" void kernel_launch(void* const* d_in, const int* in_sizes, int n_in,
                              void* d_out, int out_size)
{
    const float* z_e = (const float*)d_in[0];
    const float* emb = (const float*)d_in[1];

    float* out  = (float*)d_out;
    float* res  = out;
    float* loss = out + 8388608;
    float* idxf = out + 8388609;

    cudaFuncSetAttribute(k_mma,  cudaFuncAttributeMaxDynamicSharedMemorySize, SMEM_MMA);
    cudaFuncSetAttribute(k_post, cudaFuncAttributeMaxDynamicSharedMemorySize, SMEM_POST);

    // order chosen so ncu (-s 5 -c 1) lands on k_mma (launch #6).
    // k_zero runs LAST: g_done is zero-initialized at load; k_post leaves it
    // at 256 and k_zero re-arms it for the next replay. Deterministic.
    k_prep <<<128, 256>>>(emb);
    k_mma  <<<dim3(NCB, N_ROWS / 128), 256, SMEM_MMA>>>(z_e);
    k_post <<<N_ROWS / 128, 256, SMEM_POST>>>(z_e, emb, res, idxf, loss);
    k_zero <<<1, 32>>>();
}